// round 4
// baseline (speedup 1.0000x reference)
#include <cuda_runtime.h>

// ---------------------------------------------------------------------------
// QuantumRNNCell fused persistent kernel, v3:
//   out[b,h] = hx[b,h] + sum_j q[b,j] * fc_w[h,j] + fc_b[h]
// 6-qubit sim packed 2 rows per warp: 16 lanes per row, 4 complex amps/lane.
// State bits: bit5,bit4 in-register (hi2 = 0..3), bits 3..0 across 16 lanes.
// Wire w touches state bit (5-w):  w=0 -> hi2 bit1, w=1 -> hi2 bit0,
// w>=2 -> lane bit (5-w) via shfl.xor mask (1<<(5-w)) < 16 (stays in group).
// a[8] = {re,im} x hi2(0..3)
// ---------------------------------------------------------------------------

#define NQ 6
#define NLAYERS 3
#define HDIM 1024
#define TR 16         // rows per tile (8 warps x 2 rows)

// ---- in-register pair gates (complex pair at hi2 indices i0, i1) -----------
__device__ __forceinline__ void rx_pair(float a[8], int i0, int i1, float c, float s) {
    float re0 = a[2*i0], im0 = a[2*i0+1], re1 = a[2*i1], im1 = a[2*i1+1];
    a[2*i0]   = c*re0 + s*im1;
    a[2*i0+1] = c*im0 - s*re1;
    a[2*i1]   = c*re1 + s*im0;
    a[2*i1+1] = c*im1 - s*re0;
}
__device__ __forceinline__ void ry_pair(float a[8], int i0, int i1, float c, float s) {
    float re0 = a[2*i0], im0 = a[2*i0+1], re1 = a[2*i1], im1 = a[2*i1+1];
    a[2*i0]   = c*re0 - s*re1;
    a[2*i0+1] = c*im0 - s*im1;
    a[2*i1]   = s*re0 + c*re1;
    a[2*i1+1] = s*im0 + c*im1;
}
__device__ __forceinline__ void rz_one(float a[8], int i, float c, float sg) {
    float re = a[2*i], im = a[2*i+1];
    a[2*i]   = c*re - sg*im;
    a[2*i+1] = c*im + sg*re;
}

// ---- shuffle gates for wires 2..5 (mask m = 1<<(5-w), within 16-lane grp) --
__device__ __forceinline__ void rx_shfl(float a[8], int m, float c, float s) {
#pragma unroll
    for (int k = 0; k < 4; k++) {
        float orr = __shfl_xor_sync(0xFFFFFFFFu, a[2*k],   m);
        float oii = __shfl_xor_sync(0xFFFFFFFFu, a[2*k+1], m);
        a[2*k]   = c*a[2*k]   + s*oii;
        a[2*k+1] = c*a[2*k+1] - s*orr;
    }
}
__device__ __forceinline__ void ry_shfl(float a[8], int m, float c, float s, unsigned lane) {
    float sg = (lane & (unsigned)m) ? s : -s;
#pragma unroll
    for (int k = 0; k < 4; k++) {
        float orr = __shfl_xor_sync(0xFFFFFFFFu, a[2*k],   m);
        float oii = __shfl_xor_sync(0xFFFFFFFFu, a[2*k+1], m);
        a[2*k]   = c*a[2*k]   + sg*orr;
        a[2*k+1] = c*a[2*k+1] + sg*oii;
    }
}
__device__ __forceinline__ void rz_shfl(float a[8], int m, float c, float s, unsigned lane) {
    float sg = (lane & (unsigned)m) ? s : -s;
#pragma unroll
    for (int k = 0; k < 4; k++) rz_one(a, k, c, sg);
}

// ---- gate dispatch (w is compile-time constant after unroll) ---------------
__device__ __forceinline__ void apply_rx(int w, float a[8], float c, float s, unsigned lane) {
    if (w == 0)      { rx_pair(a, 0, 2, c, s); rx_pair(a, 1, 3, c, s); }
    else if (w == 1) { rx_pair(a, 0, 1, c, s); rx_pair(a, 2, 3, c, s); }
    else             rx_shfl(a, 1 << (5 - w), c, s);
}
__device__ __forceinline__ void apply_ry(int w, float a[8], float c, float s, unsigned lane) {
    if (w == 0)      { ry_pair(a, 0, 2, c, s); ry_pair(a, 1, 3, c, s); }
    else if (w == 1) { ry_pair(a, 0, 1, c, s); ry_pair(a, 2, 3, c, s); }
    else             ry_shfl(a, 1 << (5 - w), c, s, lane);
}
__device__ __forceinline__ void apply_rz(int w, float a[8], float c, float s, unsigned lane) {
    if (w == 0) {        // bit5 = hi2 bit1: hi2 0,1 -> -s ; 2,3 -> +s
        rz_one(a, 0, c, -s); rz_one(a, 1, c, -s);
        rz_one(a, 2, c,  s); rz_one(a, 3, c,  s);
    } else if (w == 1) { // bit4 = hi2 bit0: hi2 0,2 -> -s ; 1,3 -> +s
        rz_one(a, 0, c, -s); rz_one(a, 2, c, -s);
        rz_one(a, 1, c,  s); rz_one(a, 3, c,  s);
    } else rz_shfl(a, 1 << (5 - w), c, s, lane);
}

// CNOT control q, target (q+1)%6
__device__ __forceinline__ void apply_cnot_ring(int q, float a[8], unsigned lane) {
    if (q == 0) {
        // control bit5 (hi2 {2,3}), target bit4: swap hi2 2 <-> 3
        float t;
        t = a[4]; a[4] = a[6]; a[6] = t;
        t = a[5]; a[5] = a[7]; a[7] = t;
    } else if (q == 1) {
        // control bit4 (hi2 {1,3}), target bit3: shuffle mask 8, unconditional
#pragma unroll
        for (int k = 1; k < 4; k += 2) {
            a[2*k]   = __shfl_xor_sync(0xFFFFFFFFu, a[2*k],   8);
            a[2*k+1] = __shfl_xor_sync(0xFFFFFFFFu, a[2*k+1], 8);
        }
    } else if (q == 5) {
        // control bit0 (lane&1), target bit5: swap hi2 {0,1} <-> {2,3}
        if (lane & 1u) {
            float t;
            t = a[0]; a[0] = a[4]; a[4] = t;
            t = a[1]; a[1] = a[5]; a[5] = t;
            t = a[2]; a[2] = a[6]; a[6] = t;
            t = a[3]; a[3] = a[7]; a[7] = t;
        }
    } else {
        // q in {2,3,4}: control lane bit (5-q), target shuffle mask 1<<(4-q)
        int cb = 1 << (5 - q);
        int tm = 1 << (4 - q);
        bool ctrl = (lane & (unsigned)cb) != 0;
#pragma unroll
        for (int k = 0; k < 4; k++) {
            float vr = __shfl_xor_sync(0xFFFFFFFFu, a[2*k],   tm);
            float vi = __shfl_xor_sync(0xFFFFFFFFu, a[2*k+1], tm);
            if (ctrl) { a[2*k] = vr; a[2*k+1] = vi; }
        }
    }
}

// ---- fused persistent kernel ------------------------------------------------
__global__ __launch_bounds__(256, 3)
void fused_kernel(const float* __restrict__ x,
                  const float* __restrict__ hx,
                  const float* __restrict__ qw,    // (3,6)
                  const float* __restrict__ fc_w,  // (1024,6)
                  const float* __restrict__ fc_b,  // (1024,)
                  float* __restrict__ out,
                  int B, int ntiles) {
    __shared__ float4 sw[NQ][HDIM / 4];
    __shared__ float4 sb[HDIM / 4];
    __shared__ float  sq[2][TR][8];
    __shared__ float  swc[NLAYERS * NQ];
    __shared__ float  sws[NLAYERS * NQ];

    const int tid = threadIdx.x;
    const int warp = tid >> 5;
    const unsigned lane = tid & 31u;
    const unsigned lane16 = lane & 15u;   // lane within 16-group
    const int half = (int)(lane >> 4);    // 0 or 1: which row of the pair

    // ---- one-time setup per persistent CTA ----
    {
        int h0 = 4 * tid;
#pragma unroll
        for (int j = 0; j < NQ; j++) {
            sw[j][tid] = make_float4(fc_w[(h0 + 0) * NQ + j],
                                     fc_w[(h0 + 1) * NQ + j],
                                     fc_w[(h0 + 2) * NQ + j],
                                     fc_w[(h0 + 3) * NQ + j]);
        }
        sb[tid] = make_float4(fc_b[h0], fc_b[h0 + 1], fc_b[h0 + 2], fc_b[h0 + 3]);
        if (tid < NLAYERS * NQ) {
            float s, c;
            __sincosf(__ldg(&qw[tid]) * 0.5f, &s, &c);
            swc[tid] = c; sws[tid] = s;
        }
    }
    __syncthreads();

    int buf = 0;
    for (int tile = blockIdx.x; tile < ntiles; tile += gridDim.x) {
        const int row0 = tile * TR;
        const int nrows = min(TR, B - row0);

        // ---- prefetch hx rows 0..7 of this tile (MLP=8, covers sim) ----
        float4 h[8];
#pragma unroll
        for (int r = 0; r < 8; r++) {
            int b = row0 + r;
            if (b < B)
                h[r] = ((const float4*)(hx + (size_t)b * HDIM))[tid];
        }

        // ---- sim: this warp handles 2 rows (one per 16-lane half) ----
        {
            const int myrow = warp * 2 + half;
            const int b = min(row0 + myrow, B - 1);

            float xc[NQ], xs[NQ];
#pragma unroll
            for (int j = 0; j < NQ; j++) {
                __sincosf(__ldg(&x[b * NQ + j]) * 0.5f, &xs[j], &xc[j]);
            }

            float a[8];
#pragma unroll
            for (int k = 0; k < 8; k++) a[k] = 0.0f;
            a[0] = (lane16 == 0) ? 1.0f : 0.0f;

#pragma unroll
            for (int i = 0; i < NQ; i++) {
                int j1 = (i + 1) % NQ, j2 = (i + 2) % NQ;
                apply_rx(i, a, xc[i], xs[i], lane);
                apply_ry(i, a, xc[j1], xs[j1], lane);
                apply_rz(i, a, xc[j2], xs[j2], lane);
            }

#pragma unroll
            for (int l = 0; l < NLAYERS; l++) {
#pragma unroll
                for (int q = 0; q < NQ; q++)
                    apply_ry(q, a, swc[l * NQ + q], sws[l * NQ + q], lane);
#pragma unroll
                for (int q = 0; q < NQ; q++) apply_cnot_ring(q, a, lane);
            }

            // probabilities per hi2
            float p0 = a[0]*a[0] + a[1]*a[1];
            float p1 = a[2]*a[2] + a[3]*a[3];
            float p2 = a[4]*a[4] + a[5]*a[5];
            float p3 = a[6]*a[6] + a[7]*a[7];
            float ptot = p0 + p1 + p2 + p3;

            float e[NQ];
            e[0] = (p0 + p1) - (p2 + p3);      // wire0: bit5 = hi2 bit1
            e[1] = (p0 - p1) + (p2 - p3);      // wire1: bit4 = hi2 bit0
#pragma unroll
            for (int j = 2; j < NQ; j++) {
                float sg = (lane16 & (unsigned)(1 << (5 - j))) ? -1.0f : 1.0f;
                e[j] = sg * ptot;
            }
            // butterfly within the 16-lane group
#pragma unroll
            for (int off = 8; off; off >>= 1) {
#pragma unroll
                for (int j = 0; j < NQ; j++)
                    e[j] += __shfl_xor_sync(0xFFFFFFFFu, e[j], off);
            }
            if (lane16 == 0) {
#pragma unroll
                for (int j = 0; j < NQ; j++) sq[buf][myrow][j] = e[j];
            }
        }
        __syncthreads();

        // ---- stream rows 0..7 from prefetched registers ----
#pragma unroll
        for (int r = 0; r < 8; r++) {
            if (r >= nrows) break;
            float q0 = sq[buf][r][0], q1 = sq[buf][r][1], q2 = sq[buf][r][2];
            float q3 = sq[buf][r][3], q4 = sq[buf][r][4], q5 = sq[buf][r][5];
            float4 v = h[r];
            float4 acc = sb[tid];
            float4 w;
            w = sw[0][tid]; acc.x += q0*w.x; acc.y += q0*w.y; acc.z += q0*w.z; acc.w += q0*w.w;
            w = sw[1][tid]; acc.x += q1*w.x; acc.y += q1*w.y; acc.z += q1*w.z; acc.w += q1*w.w;
            w = sw[2][tid]; acc.x += q2*w.x; acc.y += q2*w.y; acc.z += q2*w.z; acc.w += q2*w.w;
            w = sw[3][tid]; acc.x += q3*w.x; acc.y += q3*w.y; acc.z += q3*w.z; acc.w += q3*w.w;
            w = sw[4][tid]; acc.x += q4*w.x; acc.y += q4*w.y; acc.z += q4*w.z; acc.w += q4*w.w;
            w = sw[5][tid]; acc.x += q5*w.x; acc.y += q5*w.y; acc.z += q5*w.z; acc.w += q5*w.w;
            v.x += acc.x; v.y += acc.y; v.z += acc.z; v.w += acc.w;
            ((float4*)(out + (size_t)(row0 + r) * HDIM))[tid] = v;
        }

        // ---- stream rows 8..15 straight from gmem (loads front-batched) ----
#pragma unroll
        for (int r = 8; r < TR; r++) {
            if (r >= nrows) break;
            float q0 = sq[buf][r][0], q1 = sq[buf][r][1], q2 = sq[buf][r][2];
            float q3 = sq[buf][r][3], q4 = sq[buf][r][4], q5 = sq[buf][r][5];
            float4 v = ((const float4*)(hx + (size_t)(row0 + r) * HDIM))[tid];
            float4 acc = sb[tid];
            float4 w;
            w = sw[0][tid]; acc.x += q0*w.x; acc.y += q0*w.y; acc.z += q0*w.z; acc.w += q0*w.w;
            w = sw[1][tid]; acc.x += q1*w.x; acc.y += q1*w.y; acc.z += q1*w.z; acc.w += q1*w.w;
            w = sw[2][tid]; acc.x += q2*w.x; acc.y += q2*w.y; acc.z += q2*w.z; acc.w += q2*w.w;
            w = sw[3][tid]; acc.x += q3*w.x; acc.y += q3*w.y; acc.z += q3*w.z; acc.w += q3*w.w;
            w = sw[4][tid]; acc.x += q4*w.x; acc.y += q4*w.y; acc.z += q4*w.z; acc.w += q4*w.w;
            w = sw[5][tid]; acc.x += q5*w.x; acc.y += q5*w.y; acc.z += q5*w.z; acc.w += q5*w.w;
            v.x += acc.x; v.y += acc.y; v.z += acc.z; v.w += acc.w;
            ((float4*)(out + (size_t)(row0 + r) * HDIM))[tid] = v;
        }

        buf ^= 1;
    }
}

// ---- launch ----------------------------------------------------------------
extern "C" void kernel_launch(void* const* d_in, const int* in_sizes, int n_in,
                              void* d_out, int out_size) {
    const float* x    = (const float*)d_in[0];   // (B,6)
    const float* hx   = (const float*)d_in[1];   // (B,1024)
    const float* qw   = (const float*)d_in[2];   // (3,6)
    const float* fc_w = (const float*)d_in[3];   // (1024,6)
    const float* fc_b = (const float*)d_in[4];   // (1024,)
    float* out = (float*)d_out;

    int B = in_sizes[0] / NQ;
    int ntiles = (B + TR - 1) / TR;

    int grid = 148 * 3;
    if (grid > ntiles) grid = ntiles;
    fused_kernel<<<grid, 256>>>(x, hx, qw, fc_w, fc_b, out, B, ntiles);
}